// round 16
// baseline (speedup 1.0000x reference)
#include <cuda_runtime.h>
#include <cuda_fp16.h>
#include <math.h>
#include <stdint.h>

// Problem constants
#define MFFT 8192
#define MH   4096
#define HDIM 512
#define BDIM 8
#define LDIM 8192
#define C8   (6.283185307179586f / 8192.0f)
#define RS2  0.70710678118654752440f
#define RHO_C 0.92387953251128675613f
#define RHO_S 0.38268343236508977173f
#define P16_C 0.98078528040323044913f
#define P16_S 0.19509032201612826785f

// Device scratch
__device__ float2 g_Kf[HDIM * 8193];                       // rfft(k, 16384) per h
__device__ __half g_T[(size_t)BDIM * 64 * HDIM * 128];     // g fp16, [b][l/128][h][l%128]
__device__ __half g_Wh[(size_t)HDIM * HDIM];               // W plain fp16 [o][h]

__device__ __forceinline__ float2 cmulf2(float2 a, float2 b) {
    return make_float2(a.x * b.x - a.y * b.y, a.x * b.y + a.y * b.x);
}
__device__ __forceinline__ float2 caddf2(float2 a, float2 b) { return make_float2(a.x + b.x, a.y + b.y); }
__device__ __forceinline__ float2 csubf2(float2 a, float2 b) { return make_float2(a.x - b.x, a.y - b.y); }
__device__ __forceinline__ float2 conjf2(float2 a) { return make_float2(a.x, -a.y); }
__device__ __forceinline__ int rev13(int k) { return (int)(__brev((unsigned)k) >> 19); }
__device__ __forceinline__ int phys(int i) { return i ^ ((i >> 5) & 31); }

// Proven radix-4 bodies
__device__ __forceinline__ void r4f(float2& A0, float2& A1, float2& A2, float2& A3, float2 w1) {
    float2 w2 = cmulf2(w1, w1);
    float2 s02 = caddf2(A0, A2), d02 = csubf2(A0, A2);
    float2 s13 = caddf2(A1, A3), d13 = csubf2(A1, A3);
    A0 = caddf2(s02, s13);
    A1 = cmulf2(csubf2(s02, s13), w2);
    float2 m  = make_float2(d02.x + d13.y, d02.y - d13.x);
    A2 = cmulf2(m, w1);
    float2 pq = make_float2(d02.x - d13.y, d02.y + d13.x);
    A3 = cmulf2(cmulf2(pq, w1), w2);
}
__device__ __forceinline__ void r4i(float2& A0, float2& A1, float2& A2, float2& A3, float2 v0) {
    float2 w  = cmulf2(v0, v0);
    float2 t1 = cmulf2(A1, w), t3 = cmulf2(A3, w);
    float2 b0 = caddf2(A0, t1), b1 = csubf2(A0, t1);
    float2 b2 = caddf2(A2, t3), b3 = csubf2(A2, t3);
    float2 e = cmulf2(b2, v0), f = cmulf2(b3, v0);
    A0 = caddf2(b0, e);
    A2 = csubf2(b0, e);
    A1 = make_float2(b1.x - f.y, b1.y + f.x);
    A3 = make_float2(b1.x + f.y, b1.y - f.x);
}
__device__ __forceinline__ void spectral_pair(int k, float2 Zk, float2 Zm, const float2* Kf,
                                              float2& outk, float2& outm) {
    float2 cZm = conjf2(Zm);
    float2 E = make_float2(0.5f * (Zk.x + cZm.x), 0.5f * (Zk.y + cZm.y));
    float2 Dd = csubf2(Zk, cZm);
    float2 O = make_float2(0.5f * Dd.y, -0.5f * Dd.x);
    float ang = (-3.14159265358979323846f / 8192.0f) * (float)k;
    float sn, cs; __sincosf(ang, &sn, &cs);
    float2 Wt = make_float2(cs, sn);
    float2 WO = cmulf2(Wt, O);
    float2 Xk = caddf2(E, WO);
    float2 Xm = conjf2(csubf2(E, WO));
    float2 Yk = cmulf2(Xk, Kf[k]);
    float2 Ym = cmulf2(Xm, Kf[MFFT - k]);
    float2 cYm = conjf2(Ym);
    float2 Ep = make_float2(0.5f * (Yk.x + cYm.x), 0.5f * (Yk.y + cYm.y));
    float2 P  = make_float2(0.5f * (Yk.x - cYm.x), 0.5f * (Yk.y - cYm.y));
    float2 Op = cmulf2(conjf2(Wt), P);
    outk = make_float2(Ep.x - Op.y, Ep.y + Op.x);
    outm = make_float2(Ep.x + Op.y, Op.x - Ep.y);
}

// Register radix-16 forward 12 levels (phases A,B,C) — proven.
__device__ void fft12_forward(float2* S, const float2* up, int tid) {
    float2 r[16];
    const float2 RHO = make_float2(RHO_C, -RHO_S);
#pragma unroll
    for (int j = 0; j < 8; j++) r[j] = up[tid + 512 * j];
    float2 wA;
    { float sn, cs; __sincosf(-C8 * (float)tid, &sn, &cs); wA = make_float2(cs, sn); }
    {
        float2 w = wA;
#pragma unroll
        for (int jp = 0; jp < 4; jp++) {
            float2 a0 = r[jp], a1 = r[jp + 4];
            float2 w1 = w, w2 = cmulf2(w, w);
            r[jp]      = caddf2(a0, a1);
            r[jp + 4]  = cmulf2(csubf2(a0, a1), w2);
            float2 m   = make_float2(a0.x + a1.y, a0.y - a1.x);
            r[jp + 8]  = cmulf2(m, w1);
            float2 pq  = make_float2(a0.x - a1.y, a0.y + a1.x);
            r[jp + 12] = cmulf2(cmulf2(pq, w1), w2);
            w = cmulf2(w, RHO);
        }
        float2 w4 = cmulf2(wA, wA); w4 = cmulf2(w4, w4);
#pragma unroll
        for (int q = 0; q < 4; q++) r4f(r[4 * q], r[4 * q + 1], r[4 * q + 2], r[4 * q + 3], w4);
    }
    {
        int pA = tid ^ (tid >> 5);
#pragma unroll
        for (int j = 0; j < 16; j++) S[(pA ^ ((j & 1) << 4)) + 512 * j] = r[j];
    }
    __syncthreads();
    {
        int bb = tid >> 5, t = tid & 31;
        int baseB = bb * 512;
        int tb = t ^ ((bb & 1) << 4);
#pragma unroll
        for (int j = 0; j < 16; j++) r[j] = S[baseB + 32 * j + (tb ^ j)];
        float2 wB;
        { float sn, cs; __sincosf(-C8 * (float)(t << 4), &sn, &cs); wB = make_float2(cs, sn); }
        {
            float2 w = wB;
#pragma unroll
            for (int jp = 0; jp < 4; jp++) {
                r4f(r[jp], r[jp + 4], r[jp + 8], r[jp + 12], w);
                w = cmulf2(w, RHO);
            }
        }
        float2 w4 = cmulf2(wB, wB); w4 = cmulf2(w4, w4);
#pragma unroll
        for (int q = 0; q < 4; q++) r4f(r[4 * q], r[4 * q + 1], r[4 * q + 2], r[4 * q + 3], w4);
#pragma unroll
        for (int j = 0; j < 16; j++) S[baseB + 32 * j + (tb ^ j)] = r[j];
    }
    __syncthreads();
    {
        int b2 = tid >> 1, t2 = tid & 1;
        int baseC = 32 * b2;
        int mC0 = b2 & 31;
#pragma unroll
        for (int j = 0; j < 16; j++) r[j] = S[baseC + ((2 * j + t2) ^ mC0)];
        {
            float2 w = t2 ? make_float2(P16_C, -P16_S) : make_float2(1.f, 0.f);
#pragma unroll
            for (int jp = 0; jp < 4; jp++) {
                r4f(r[jp], r[jp + 4], r[jp + 8], r[jp + 12], w);
                w = cmulf2(w, RHO);
            }
        }
        {
            float2 w1 = t2 ? make_float2(RS2, -RS2) : make_float2(1.f, 0.f);
#pragma unroll
            for (int q = 0; q < 4; q++) r4f(r[4 * q], r[4 * q + 1], r[4 * q + 2], r[4 * q + 3], w1);
        }
#pragma unroll
        for (int j = 0; j < 16; j++) S[baseC + ((2 * j + t2) ^ mC0)] = r[j];
    }
    __syncthreads();
}

// Kernel A: Kf[h] (R15, proven)
extern "C" __global__ void __launch_bounds__(512, 2) kf_kernel(const float* __restrict__ kin) {
    extern __shared__ float2 sh[];
    float2* S = sh;
    int tid = threadIdx.x;
    int h = blockIdx.x;
    const float2* kp = (const float2*)(kin + (size_t)h * LDIM);
    fft12_forward(S, kp, tid);
    float2* outp = g_Kf + (size_t)h * 8193;
#pragma unroll 1
    for (int p = 0; p < 8; p++) {
        int k = tid + 512 * p;
        if (k == 0) {
            float2 P0 = S[phys(0)], P1 = S[phys(1)];
            float2 Z0 = caddf2(P0, P1);
            float2 Zq = csubf2(P0, P1);
            outp[0]    = make_float2(Z0.x + Z0.y, 0.f);
            outp[8192] = make_float2(Z0.x - Z0.y, 0.f);
            outp[4096] = conjf2(Zq);
        } else {
            int rk = rev13(k);
            int rq = rev13(4096 - k);
            float2 Pa = S[phys(rk)], Pb = S[phys(rk + 1)];
            float2 Pc = S[phys(rq)], Pd = S[phys(rq + 1)];
            float2 Zk = caddf2(Pa, Pb);
            float2 Zm = csubf2(Pc, Pd);
            float2 cZm = conjf2(Zm);
            float2 E  = make_float2(0.5f * (Zk.x + cZm.x), 0.5f * (Zk.y + cZm.y));
            float2 Dd = csubf2(Zk, cZm);
            float2 O  = make_float2(0.5f * Dd.y, -0.5f * Dd.x);
            float ang = (-3.14159265358979323846f / 8192.0f) * (float)k;
            float sn, cs; __sincosf(ang, &sn, &cs);
            float2 Wt = make_float2(cs, sn);
            float2 WO = cmulf2(Wt, O);
            outp[k]        = caddf2(E, WO);
            outp[MFFT - k] = conjf2(csubf2(E, WO));
        }
    }
}

// Kernel B: conv for one batch b (R15 body, b as parameter, grid = HDIM)
extern "C" __global__ void __launch_bounds__(512, 2) conv_kernel(
    const float* __restrict__ u, const float* __restrict__ Dv, int bpar) {
    extern __shared__ float2 sh[];
    float2* S = sh;
    int tid = threadIdx.x;
    int b = bpar;
    int h = blockIdx.x;
    const float2* up = (const float2*)(u + ((size_t)b * HDIM + h) * LDIM);
    float2 r[16];
    const float2 RHOc = make_float2(RHO_C, RHO_S);

    fft12_forward(S, up, tid);

    const float2* Kf = g_Kf + (size_t)h * 8193;
#pragma unroll 1
    for (int p = 0; p < 4; p++) {
        int k = tid + 512 * p;
        if (k == 0) {
            float2 P0 = S[phys(0)], P1 = S[phys(1)];
            float2 Z0 = caddf2(P0, P1);
            float2 Zq = csubf2(P0, P1);
            float X0 = Z0.x + Z0.y;
            float XM = Z0.x - Z0.y;
            float2 K0 = Kf[0], KM = Kf[8192];
            float2 Y0 = make_float2(X0 * K0.x, X0 * K0.y);
            float2 YM = make_float2(XM * KM.x, XM * KM.y);
            float2 cYM = conjf2(YM);
            float2 Ep = make_float2(0.5f * (Y0.x + cYM.x), 0.5f * (Y0.y + cYM.y));
            float2 Op = make_float2(0.5f * (Y0.x - cYM.x), 0.5f * (Y0.y - cYM.y));
            S[phys(0)] = make_float2(Ep.x - Op.y, Ep.y + Op.x);
            float2 Yq = cmulf2(conjf2(Zq), Kf[4096]);
            S[phys(1)] = conjf2(Yq);
            float2 P2 = S[phys(2)], P3 = S[phys(3)];
            float2 Zk = caddf2(P2, P3);
            float2 Zm = csubf2(P2, P3);
            float2 ok, om;
            spectral_pair(2048, Zk, Zm, Kf, ok, om);
            S[phys(2)] = ok;
            S[phys(3)] = om;
        } else {
            int rk  = rev13(k);
            int rkt = rev13(4096 - k);
            float2 Pa = S[phys(rk)],  Pb = S[phys(rk + 1)];
            float2 Pc = S[phys(rkt)], Pd = S[phys(rkt + 1)];
            float2 Zk   = caddf2(Pa, Pb);
            float2 ZMk  = csubf2(Pc, Pd);
            float2 Zkt  = caddf2(Pc, Pd);
            float2 ZMkt = csubf2(Pa, Pb);
            float2 o1k, o1m, o2k, o2m;
            spectral_pair(k, Zk, ZMk, Kf, o1k, o1m);
            spectral_pair(4096 - k, Zkt, ZMkt, Kf, o2k, o2m);
            S[phys(rk)]      = o1k;
            S[phys(rkt + 1)] = o1m;
            S[phys(rkt)]     = o2k;
            S[phys(rk + 1)]  = o2m;
        }
    }

    __syncthreads();
    {
        int baseCi = 32 * (tid >> 1);
        int mm = (16 * (tid & 1)) ^ ((tid >> 1) & 31);
#pragma unroll
        for (int j = 0; j < 16; j++) r[j] = S[baseCi + (j ^ mm)];
#pragma unroll
        for (int m2 = 0; m2 < 8; m2++) {
            float2 a = r[2 * m2], bq = r[2 * m2 + 1];
            r[2 * m2]     = caddf2(a, bq);
            r[2 * m2 + 1] = csubf2(a, bq);
        }
#pragma unroll
        for (int q = 0; q < 2; q++)
#pragma unroll
            for (int tq = 0; tq < 2; tq++) {
                float2 v0 = tq ? make_float2(RS2, RS2) : make_float2(1.f, 0.f);
                int o = 8 * q + tq;
                r4i(r[o], r[o + 2], r[o + 4], r[o + 6], v0);
            }
        {
            float2 wb = make_float2(1.f, 0.f);
#pragma unroll
            for (int j = 0; j < 8; j++) {
                float2 t = cmulf2(r[j + 8], wb);
                float2 a = r[j];
                r[j]     = caddf2(a, t);
                r[j + 8] = csubf2(a, t);
                wb = cmulf2(wb, RHOc);
            }
        }
#pragma unroll
        for (int j = 0; j < 16; j++) S[baseCi + (j ^ mm)] = r[j];
    }

    __syncthreads();
    {
        int c = tid >> 4, i0 = tid & 15;
        int baseBi = 256 * c;
        int mB = i0 ^ (8 * (c & 3));
#pragma unroll
        for (int j = 0; j < 16; j++)
            r[j] = S[baseBi + 32 * (j >> 1) + (mB ^ ((16 * (j & 1)) | (j >> 1)))];
        float2 qB;
        { float sn, cs; __sincosf(C8 * (float)(i0 << 5), &sn, &cs); qB = make_float2(cs, sn); }
        {
            float2 v0 = cmulf2(qB, qB); v0 = cmulf2(v0, v0);
#pragma unroll
            for (int q = 0; q < 4; q++) r4i(r[4 * q], r[4 * q + 1], r[4 * q + 2], r[4 * q + 3], v0);
        }
        {
            float2 v = qB;
#pragma unroll
            for (int jp = 0; jp < 4; jp++) {
                r4i(r[jp], r[jp + 4], r[jp + 8], r[jp + 12], v);
                v = cmulf2(v, RHOc);
            }
        }
#pragma unroll
        for (int j = 0; j < 16; j++)
            S[baseBi + 32 * (j >> 1) + (mB ^ ((16 * (j & 1)) | (j >> 1)))] = r[j];
    }

    __syncthreads();
    {
        int e = tid >> 8, i1 = tid & 255;
        int baseA = 4096 * e + (i1 & ~31);
        int mA = (i1 & 31) ^ (i1 >> 5);
#pragma unroll
        for (int j = 0; j < 16; j++) r[j] = S[baseA + 256 * j + (mA ^ (8 * (j & 3)))];
        float2 qA;
        { float sn, cs; __sincosf(C8 * (float)(i1 << 1), &sn, &cs); qA = make_float2(cs, sn); }
        {
            float2 v0 = cmulf2(qA, qA); v0 = cmulf2(v0, v0);
#pragma unroll
            for (int q = 0; q < 4; q++) r4i(r[4 * q], r[4 * q + 1], r[4 * q + 2], r[4 * q + 3], v0);
        }
        {
            float2 v = qA;
#pragma unroll
            for (int jp = 0; jp < 4; jp++) {
                r4i(r[jp], r[jp + 4], r[jp + 8], r[jp + 12], v);
                v = cmulf2(v, RHOc);
            }
        }
#pragma unroll
        for (int j = 0; j < 16; j++) S[baseA + 256 * j + (mA ^ (8 * (j & 3)))] = r[j];
    }

    __syncthreads();
    float Dh = Dv[h];
    const float inv = 1.0f / (float)MFFT;
    int pA = tid ^ (tid >> 5);
    float2 wb;
    { float sn, cs; __sincosf(C8 * (float)tid, &sn, &cs); wb = make_float2(cs, sn); }
#pragma unroll
    for (int p = 0; p < 8; p++) {
        int addr = (pA ^ ((p & 1) << 4)) + 512 * p;
        float2 a = S[addr], bq = S[addr + 4096];
        float2 t = cmulf2(bq, wb);
        float2 X = caddf2(a, t);
        int g = tid + 512 * p;
        float2 uu = up[g];
        float y0 = X.x * inv + Dh * uu.x;
        float y1 = X.y * inv + Dh * uu.y;
        float q0 = 0.5f * y0 * (1.0f + erff(y0 * 0.70710678118654752440f));
        float q1 = 0.5f * y1 * (1.0f + erff(y1 * 0.70710678118654752440f));
        __half2* gt = (__half2*)g_T + (((size_t)b * 64 + (g >> 6)) * HDIM + h) * 64 + (g & 63);
        *gt = __floats2half2_rn(q0, q1);
        wb = cmulf2(wb, RHOc);
    }
}

// W pack: plain fp16
extern "C" __global__ void __launch_bounds__(256) wpack_kernel(const float* __restrict__ Wm) {
    int i = blockIdx.x * 256 + threadIdx.x;
    g_Wh[i] = __float2half_rn(Wm[i]);
}

// ---------------- mma.sync GEMM (R15, b as parameter, grid (4,64,1)) ----------------
__device__ __forceinline__ uint32_t smem_u32(const void* p) {
    return (uint32_t)__cvta_generic_to_shared(p);
}
__device__ __forceinline__ uint32_t swz(uint32_t off) { return off ^ ((off >> 3) & 0x70); }
__device__ __forceinline__ uint32_t swzB(uint32_t row, uint32_t colb) {
    return row * 256 + (colb ^ ((row & 7) << 4));
}

__device__ __forceinline__ void ldmat4(uint32_t* r, uint32_t addr) {
    asm volatile("ldmatrix.sync.aligned.m8n8.x4.shared.b16 {%0,%1,%2,%3}, [%4];"
                 : "=r"(r[0]), "=r"(r[1]), "=r"(r[2]), "=r"(r[3]) : "r"(addr));
}
__device__ __forceinline__ void ldmat4t(uint32_t* r, uint32_t addr) {
    asm volatile("ldmatrix.sync.aligned.m8n8.x4.trans.shared.b16 {%0,%1,%2,%3}, [%4];"
                 : "=r"(r[0]), "=r"(r[1]), "=r"(r[2]), "=r"(r[3]) : "r"(addr));
}
__device__ __forceinline__ void mma16816(float* d, const uint32_t* a, uint32_t b0, uint32_t b1) {
    asm volatile(
        "mma.sync.aligned.m16n8k16.row.col.f32.f16.f16.f32 "
        "{%0,%1,%2,%3}, {%4,%5,%6,%7}, {%8,%9}, {%0,%1,%2,%3};"
        : "+f"(d[0]), "+f"(d[1]), "+f"(d[2]), "+f"(d[3])
        : "r"(a[0]), "r"(a[1]), "r"(a[2]), "r"(a[3]), "r"(b0), "r"(b1));
}
#define CP16(dst, src) asm volatile("cp.async.cg.shared.global [%0], [%1], 16;" :: "r"(dst), "l"(src) : "memory")
#define CP_COMMIT()    asm volatile("cp.async.commit_group;" ::: "memory")
#define CP_WAIT1()     asm volatile("cp.async.wait_group 1;" ::: "memory")

extern "C" __global__ void __launch_bounds__(256, 2) gemm_mma_kernel(
    const float* __restrict__ bias, float* __restrict__ outp, int bpar) {
    extern __shared__ char smem[];
    uint32_t sb = smem_u32(smem);
    int t = threadIdx.x;
    int lane = t & 31, wid = t >> 5;
    int warp_m = wid >> 2, warp_n = wid & 3;
    int o0 = blockIdx.x * 128, l0 = blockIdx.y * 128, b = bpar;

    int a_row = t >> 1, a_half = t & 1;
    const __half* wp = g_Wh + (size_t)(o0 + a_row) * HDIM + a_half * 32;
    int b_row = t >> 2, b_c4 = t & 3;
    const __half* gpB = g_T + ((size_t)b * 64 + blockIdx.y) * HDIM * 128;

    auto load_chunk = [&](int dc) {
        int buf = dc % 3;
        uint32_t sA = sb + buf * 32768;
        uint32_t sB = sA + 16384;
        const __half* aw = wp + dc * 64;
#pragma unroll
        for (int j = 0; j < 4; j++) {
            uint32_t off = (uint32_t)(a_row * 128 + a_half * 64 + j * 16);
            CP16(sA + swz(off), aw + j * 8);
        }
        const __half* brow = gpB + (size_t)(dc * 64 + b_row) * 128 + b_c4 * 32;
#pragma unroll
        for (int e2 = 0; e2 < 4; e2++) {
            uint32_t colb = (uint32_t)(b_c4 * 64 + e2 * 16);
            CP16(sB + swzB((uint32_t)b_row, colb), brow + e2 * 8);
        }
    };

    int a_lrow = (lane & 7) + ((lane >> 3) & 1) * 8;
    int a_lcol = (lane >> 4) * 16;
    uint32_t xorm = (uint32_t)((lane & 7) << 4);
    int bt_row = (lane & 7) + 8 * ((lane >> 3) & 1);
    int bt_colb = 16 * (lane >> 4);

    float acc[4][4][4];
#pragma unroll
    for (int i = 0; i < 4; i++)
#pragma unroll
        for (int j = 0; j < 4; j++)
#pragma unroll
            for (int q = 0; q < 4; q++) acc[i][j][q] = 0.f;

    load_chunk(0);
    CP_COMMIT();
    load_chunk(1);
    CP_COMMIT();

#pragma unroll 1
    for (int dc = 0; dc < 8; dc++) {
        CP_WAIT1();
        __syncthreads();
        if (dc + 2 < 8) load_chunk(dc + 2);
        CP_COMMIT();
        int buf = dc % 3;
        uint32_t sA = sb + buf * 32768;
        uint32_t sB = sA + 16384;
#pragma unroll
        for (int st = 0; st < 4; st++) {
            int cc = st >> 1, sub = st & 1;
            uint32_t afr[4][4];
#pragma unroll
            for (int mt = 0; mt < 4; mt++) {
                uint32_t off = (uint32_t)((warp_m * 64 + mt * 16 + a_lrow) * 128
                                          + cc * 64 + sub * 32 + a_lcol);
                ldmat4(afr[mt], sA + (off ^ xorm));
            }
#pragma unroll
            for (int bt = 0; bt < 2; bt++) {
                uint32_t bfr[4];
                uint32_t row = (uint32_t)(st * 16 + bt_row);
                uint32_t colb = (uint32_t)(2 * (warp_n * 32 + bt * 16) + bt_colb);
                ldmat4t(bfr, sB + swzB(row, colb));
#pragma unroll
                for (int mt = 0; mt < 4; mt++) {
                    mma16816(acc[mt][bt * 2 + 0], afr[mt], bfr[0], bfr[1]);
                    mma16816(acc[mt][bt * 2 + 1], afr[mt], bfr[2], bfr[3]);
                }
            }
        }
    }

#pragma unroll
    for (int mt = 0; mt < 4; mt++) {
        int r = o0 + warp_m * 64 + mt * 16 + (lane >> 2);
        float bs0 = bias[r], bs1 = bias[r + 8];
        float* p0 = outp + ((size_t)b * HDIM + r) * LDIM + l0 + warp_n * 32 + (lane & 3) * 2;
        float* p1 = p0 + 8 * LDIM;
#pragma unroll
        for (int nt = 0; nt < 4; nt++) {
            float2 v0 = make_float2(acc[mt][nt][0] + bs0, acc[mt][nt][1] + bs0);
            float2 v1 = make_float2(acc[mt][nt][2] + bs1, acc[mt][nt][3] + bs1);
            *(float2*)(p0 + nt * 8) = v0;
            *(float2*)(p1 + nt * 8) = v1;
        }
    }
}

extern "C" void kernel_launch(void* const* d_in, const int* in_sizes, int n_in,
                              void* d_out, int out_size) {
    const float* u    = (const float*)d_in[0];   // (8,512,8192)
    const float* kin  = (const float*)d_in[1];   // (1,512,8192)
    const float* Dv   = (const float*)d_in[2];   // (1,512)
    const float* Wm   = (const float*)d_in[3];   // (512,512)
    const float* bias = (const float*)d_in[4];   // (512,)
    float* outp = (float*)d_out;                 // (8,512,8192)

    // Lazily created host-side stream/event objects (no device memory).
    static cudaStream_t s1 = 0;
    static cudaEvent_t evb[BDIM];
    static cudaEvent_t evJoin = 0;
    static int inited = 0;
    if (!inited) {
        if (cudaStreamCreateWithFlags(&s1, cudaStreamNonBlocking) != cudaSuccess) s1 = 0;
        for (int i = 0; i < BDIM; i++)
            cudaEventCreateWithFlags(&evb[i], cudaEventDisableTiming);
        cudaEventCreateWithFlags(&evJoin, cudaEventDisableTiming);
        inited = 1;
    }

    size_t smem = (size_t)MFFT * sizeof(float2);  // 64 KB
    cudaFuncSetAttribute(kf_kernel,   cudaFuncAttributeMaxDynamicSharedMemorySize, (int)smem);
    cudaFuncSetAttribute(conv_kernel, cudaFuncAttributeMaxDynamicSharedMemorySize, (int)smem);
    size_t gsmem = 3 * 32768;                      // 96 KB
    cudaFuncSetAttribute(gemm_mma_kernel, cudaFuncAttributeMaxDynamicSharedMemorySize, (int)gsmem);

    wpack_kernel<<<HDIM * HDIM / 256, 256>>>(Wm);
    kf_kernel<<<HDIM, 512, smem>>>(kin);

    dim3 ggrid(HDIM / 128, LDIM / 128, 1);
    if (s1) {
        // Fork/join: conv_b on main stream; gemm_b on s1 gated by event after conv_b.
        for (int b = 0; b < BDIM; b++) {
            conv_kernel<<<HDIM, 512, smem>>>(u, Dv, b);
            cudaEventRecord(evb[b], 0);
            cudaStreamWaitEvent(s1, evb[b], 0);
            gemm_mma_kernel<<<ggrid, 256, gsmem, s1>>>(bias, outp, b);
        }
        cudaEventRecord(evJoin, s1);
        cudaStreamWaitEvent(0, evJoin, 0);
    } else {
        for (int b = 0; b < BDIM; b++) {
            conv_kernel<<<HDIM, 512, smem>>>(u, Dv, b);
            gemm_mma_kernel<<<ggrid, 256, gsmem>>>(bias, outp, b);
        }
    }
}

// round 17
// speedup vs baseline: 1.1874x; 1.1874x over previous
#include <cuda_runtime.h>
#include <cuda_fp16.h>
#include <math.h>
#include <stdint.h>

// Problem constants
#define MFFT 8192
#define MH   4096
#define HDIM 512
#define BDIM 8
#define LDIM 8192
#define C8   (6.283185307179586f / 8192.0f)
#define RS2  0.70710678118654752440f
#define RHO_C 0.92387953251128675613f
#define RHO_S 0.38268343236508977173f
#define P16_C 0.98078528040323044913f
#define P16_S 0.19509032201612826785f
#define SCL  (1.0f / 8192.0f)

// Device scratch
__device__ float2 g_Kf[HDIM * 8193];                       // rfft(k,16384)/8192 per h (prescaled)
__device__ __half g_T[(size_t)BDIM * 64 * HDIM * 128];     // g fp16, [b][l/128][h][l%128]
__device__ __half g_Wh[(size_t)HDIM * HDIM];               // W plain fp16 [o][h]

__device__ __forceinline__ float2 cmulf2(float2 a, float2 b) {
    return make_float2(a.x * b.x - a.y * b.y, a.x * b.y + a.y * b.x);
}
__device__ __forceinline__ float2 caddf2(float2 a, float2 b) { return make_float2(a.x + b.x, a.y + b.y); }
__device__ __forceinline__ float2 csubf2(float2 a, float2 b) { return make_float2(a.x - b.x, a.y - b.y); }
__device__ __forceinline__ float2 conjf2(float2 a) { return make_float2(a.x, -a.y); }
__device__ __forceinline__ int rev13(int k) { return (int)(__brev((unsigned)k) >> 19); }
__device__ __forceinline__ int phys(int i) { return i ^ ((i >> 5) & 31); }

// Proven radix-4 bodies
__device__ __forceinline__ void r4f(float2& A0, float2& A1, float2& A2, float2& A3, float2 w1) {
    float2 w2 = cmulf2(w1, w1);
    float2 s02 = caddf2(A0, A2), d02 = csubf2(A0, A2);
    float2 s13 = caddf2(A1, A3), d13 = csubf2(A1, A3);
    A0 = caddf2(s02, s13);
    A1 = cmulf2(csubf2(s02, s13), w2);
    float2 m  = make_float2(d02.x + d13.y, d02.y - d13.x);
    A2 = cmulf2(m, w1);
    float2 pq = make_float2(d02.x - d13.y, d02.y + d13.x);
    A3 = cmulf2(cmulf2(pq, w1), w2);
}
__device__ __forceinline__ void r4i(float2& A0, float2& A1, float2& A2, float2& A3, float2 v0) {
    float2 w  = cmulf2(v0, v0);
    float2 t1 = cmulf2(A1, w), t3 = cmulf2(A3, w);
    float2 b0 = caddf2(A0, t1), b1 = csubf2(A0, t1);
    float2 b2 = caddf2(A2, t3), b3 = csubf2(A2, t3);
    float2 e = cmulf2(b2, v0), f = cmulf2(b3, v0);
    A0 = caddf2(b0, e);
    A2 = csubf2(b0, e);
    A1 = make_float2(b1.x - f.y, b1.y + f.x);
    A3 = make_float2(b1.x + f.y, b1.y - f.x);
}
// Spectral pair with explicit Wt = e^{-i*pi*k/8192}
__device__ __forceinline__ void spectral_pair_w(float2 Wt, int k, float2 Zk, float2 Zm,
                                                const float2* Kf, float2& outk, float2& outm) {
    float2 cZm = conjf2(Zm);
    float2 E = make_float2(0.5f * (Zk.x + cZm.x), 0.5f * (Zk.y + cZm.y));
    float2 Dd = csubf2(Zk, cZm);
    float2 O = make_float2(0.5f * Dd.y, -0.5f * Dd.x);
    float2 WO = cmulf2(Wt, O);
    float2 Xk = caddf2(E, WO);
    float2 Xm = conjf2(csubf2(E, WO));
    float2 Yk = cmulf2(Xk, Kf[k]);
    float2 Ym = cmulf2(Xm, Kf[MFFT - k]);
    float2 cYm = conjf2(Ym);
    float2 Ep = make_float2(0.5f * (Yk.x + cYm.x), 0.5f * (Yk.y + cYm.y));
    float2 P  = make_float2(0.5f * (Yk.x - cYm.x), 0.5f * (Yk.y - cYm.y));
    float2 Op = cmulf2(conjf2(Wt), P);
    outk = make_float2(Ep.x - Op.y, Ep.y + Op.x);
    outm = make_float2(Ep.x + Op.y, Op.x - Ep.y);
}
__device__ __forceinline__ void spectral_pair(int k, float2 Zk, float2 Zm, const float2* Kf,
                                              float2& outk, float2& outm) {
    float ang = (-3.14159265358979323846f / 8192.0f) * (float)k;
    float sn, cs; __sincosf(ang, &sn, &cs);
    spectral_pair_w(make_float2(cs, sn), k, Zk, Zm, Kf, outk, outm);
}

// Register radix-16 forward 12 levels (phases A,B,C) — proven.
__device__ void fft12_forward(float2* S, const float2* up, int tid) {
    float2 r[16];
    const float2 RHO = make_float2(RHO_C, -RHO_S);
#pragma unroll
    for (int j = 0; j < 8; j++) r[j] = up[tid + 512 * j];
    float2 wA;
    { float sn, cs; __sincosf(-C8 * (float)tid, &sn, &cs); wA = make_float2(cs, sn); }
    {
        float2 w = wA;
#pragma unroll
        for (int jp = 0; jp < 4; jp++) {
            float2 a0 = r[jp], a1 = r[jp + 4];
            float2 w1 = w, w2 = cmulf2(w, w);
            r[jp]      = caddf2(a0, a1);
            r[jp + 4]  = cmulf2(csubf2(a0, a1), w2);
            float2 m   = make_float2(a0.x + a1.y, a0.y - a1.x);
            r[jp + 8]  = cmulf2(m, w1);
            float2 pq  = make_float2(a0.x - a1.y, a0.y + a1.x);
            r[jp + 12] = cmulf2(cmulf2(pq, w1), w2);
            w = cmulf2(w, RHO);
        }
        float2 w4 = cmulf2(wA, wA); w4 = cmulf2(w4, w4);
#pragma unroll
        for (int q = 0; q < 4; q++) r4f(r[4 * q], r[4 * q + 1], r[4 * q + 2], r[4 * q + 3], w4);
    }
    {
        int pA = tid ^ (tid >> 5);
#pragma unroll
        for (int j = 0; j < 16; j++) S[(pA ^ ((j & 1) << 4)) + 512 * j] = r[j];
    }
    __syncthreads();
    {
        int bb = tid >> 5, t = tid & 31;
        int baseB = bb * 512;
        int tb = t ^ ((bb & 1) << 4);
#pragma unroll
        for (int j = 0; j < 16; j++) r[j] = S[baseB + 32 * j + (tb ^ j)];
        float2 wB;
        { float sn, cs; __sincosf(-C8 * (float)(t << 4), &sn, &cs); wB = make_float2(cs, sn); }
        {
            float2 w = wB;
#pragma unroll
            for (int jp = 0; jp < 4; jp++) {
                r4f(r[jp], r[jp + 4], r[jp + 8], r[jp + 12], w);
                w = cmulf2(w, RHO);
            }
        }
        float2 w4 = cmulf2(wB, wB); w4 = cmulf2(w4, w4);
#pragma unroll
        for (int q = 0; q < 4; q++) r4f(r[4 * q], r[4 * q + 1], r[4 * q + 2], r[4 * q + 3], w4);
#pragma unroll
        for (int j = 0; j < 16; j++) S[baseB + 32 * j + (tb ^ j)] = r[j];
    }
    __syncthreads();
    {
        int b2 = tid >> 1, t2 = tid & 1;
        int baseC = 32 * b2;
        int mC0 = b2 & 31;
#pragma unroll
        for (int j = 0; j < 16; j++) r[j] = S[baseC + ((2 * j + t2) ^ mC0)];
        {
            float2 w = t2 ? make_float2(P16_C, -P16_S) : make_float2(1.f, 0.f);
#pragma unroll
            for (int jp = 0; jp < 4; jp++) {
                r4f(r[jp], r[jp + 4], r[jp + 8], r[jp + 12], w);
                w = cmulf2(w, RHO);
            }
        }
        {
            float2 w1 = t2 ? make_float2(RS2, -RS2) : make_float2(1.f, 0.f);
#pragma unroll
            for (int q = 0; q < 4; q++) r4f(r[4 * q], r[4 * q + 1], r[4 * q + 2], r[4 * q + 3], w1);
        }
#pragma unroll
        for (int j = 0; j < 16; j++) S[baseC + ((2 * j + t2) ^ mC0)] = r[j];
    }
    __syncthreads();
}

// Kernel A: Kf[h] = rfft(k[h], 16384) * (1/8192), prescaled for conv.
extern "C" __global__ void __launch_bounds__(512, 2) kf_kernel(const float* __restrict__ kin) {
    extern __shared__ float2 sh[];
    float2* S = sh;
    int tid = threadIdx.x;
    int h = blockIdx.x;
    const float2* kp = (const float2*)(kin + (size_t)h * LDIM);
    fft12_forward(S, kp, tid);
    float2* outp = g_Kf + (size_t)h * 8193;
#pragma unroll 1
    for (int p = 0; p < 8; p++) {
        int k = tid + 512 * p;
        if (k == 0) {
            float2 P0 = S[phys(0)], P1 = S[phys(1)];
            float2 Z0 = caddf2(P0, P1);
            float2 Zq = csubf2(P0, P1);
            outp[0]    = make_float2(SCL * (Z0.x + Z0.y), 0.f);
            outp[8192] = make_float2(SCL * (Z0.x - Z0.y), 0.f);
            outp[4096] = make_float2(SCL * Zq.x, -SCL * Zq.y);
        } else {
            int rk = rev13(k);
            int rq = rev13(4096 - k);
            float2 Pa = S[phys(rk)], Pb = S[phys(rk + 1)];
            float2 Pc = S[phys(rq)], Pd = S[phys(rq + 1)];
            float2 Zk = caddf2(Pa, Pb);
            float2 Zm = csubf2(Pc, Pd);
            float2 cZm = conjf2(Zm);
            float2 E  = make_float2(0.5f * (Zk.x + cZm.x), 0.5f * (Zk.y + cZm.y));
            float2 Dd = csubf2(Zk, cZm);
            float2 O  = make_float2(0.5f * Dd.y, -0.5f * Dd.x);
            float ang = (-3.14159265358979323846f / 8192.0f) * (float)k;
            float sn, cs; __sincosf(ang, &sn, &cs);
            float2 Wt = make_float2(cs, sn);
            float2 WO = cmulf2(Wt, O);
            float2 Xk = caddf2(E, WO);
            float2 Xm = conjf2(csubf2(E, WO));
            outp[k]        = make_float2(SCL * Xk.x, SCL * Xk.y);
            outp[MFFT - k] = make_float2(SCL * Xm.x, SCL * Xm.y);
        }
    }
}

// ---------------- Kernel B: register radix-16 conv (R15 + twiddle reuse + prescale) ----
extern "C" __global__ void __launch_bounds__(512, 2) conv_kernel(
    const float* __restrict__ u, const float* __restrict__ Dv) {
    extern __shared__ float2 sh[];
    float2* S = sh;
    int tid = threadIdx.x;
    int b = blockIdx.x & (BDIM - 1);
    int h = blockIdx.x >> 3;
    const float2* up = (const float2*)(u + ((size_t)b * HDIM + h) * LDIM);
    float2 r[16];
    const float2 RHOc = make_float2(RHO_C, RHO_S);

    fft12_forward(S, up, tid);

    const float2* Kf = g_Kf + (size_t)h * 8193;
#pragma unroll 1
    for (int p = 0; p < 4; p++) {
        int k = tid + 512 * p;
        if (k == 0) {
            float2 P0 = S[phys(0)], P1 = S[phys(1)];
            float2 Z0 = caddf2(P0, P1);
            float2 Zq = csubf2(P0, P1);
            float X0 = Z0.x + Z0.y;
            float XM = Z0.x - Z0.y;
            float2 K0 = Kf[0], KM = Kf[8192];
            float2 Y0 = make_float2(X0 * K0.x, X0 * K0.y);
            float2 YM = make_float2(XM * KM.x, XM * KM.y);
            float2 cYM = conjf2(YM);
            float2 Ep = make_float2(0.5f * (Y0.x + cYM.x), 0.5f * (Y0.y + cYM.y));
            float2 Op = make_float2(0.5f * (Y0.x - cYM.x), 0.5f * (Y0.y - cYM.y));
            S[phys(0)] = make_float2(Ep.x - Op.y, Ep.y + Op.x);
            float2 Yq = cmulf2(conjf2(Zq), Kf[4096]);
            S[phys(1)] = conjf2(Yq);
            float2 P2 = S[phys(2)], P3 = S[phys(3)];
            float2 Zk = caddf2(P2, P3);
            float2 Zm = csubf2(P2, P3);
            float2 ok, om;
            spectral_pair(2048, Zk, Zm, Kf, ok, om);
            S[phys(2)] = ok;
            S[phys(3)] = om;
        } else {
            int rk  = rev13(k);
            int rkt = rev13(4096 - k);
            float2 Pa = S[phys(rk)],  Pb = S[phys(rk + 1)];
            float2 Pc = S[phys(rkt)], Pd = S[phys(rkt + 1)];
            float2 Zk   = caddf2(Pa, Pb);
            float2 ZMk  = csubf2(Pc, Pd);
            float2 Zkt  = caddf2(Pc, Pd);
            float2 ZMkt = csubf2(Pa, Pb);
            float ang = (-3.14159265358979323846f / 8192.0f) * (float)k;
            float sn, cs; __sincosf(ang, &sn, &cs);
            float2 Wt1 = make_float2(cs, sn);
            float2 Wt2 = make_float2(-Wt1.y, -Wt1.x);   // Wt(4096-k)
            float2 o1k, o1m, o2k, o2m;
            spectral_pair_w(Wt1, k, Zk, ZMk, Kf, o1k, o1m);
            spectral_pair_w(Wt2, 4096 - k, Zkt, ZMkt, Kf, o2k, o2m);
            S[phys(rk)]      = o1k;
            S[phys(rkt + 1)] = o1m;
            S[phys(rkt)]     = o2k;
            S[phys(rk + 1)]  = o2m;
        }
    }

    __syncthreads();
    {
        int baseCi = 32 * (tid >> 1);
        int mm = (16 * (tid & 1)) ^ ((tid >> 1) & 31);
#pragma unroll
        for (int j = 0; j < 16; j++) r[j] = S[baseCi + (j ^ mm)];
#pragma unroll
        for (int m2 = 0; m2 < 8; m2++) {
            float2 a = r[2 * m2], bq = r[2 * m2 + 1];
            r[2 * m2]     = caddf2(a, bq);
            r[2 * m2 + 1] = csubf2(a, bq);
        }
#pragma unroll
        for (int q = 0; q < 2; q++)
#pragma unroll
            for (int tq = 0; tq < 2; tq++) {
                float2 v0 = tq ? make_float2(RS2, RS2) : make_float2(1.f, 0.f);
                int o = 8 * q + tq;
                r4i(r[o], r[o + 2], r[o + 4], r[o + 6], v0);
            }
        {
            float2 wb = make_float2(1.f, 0.f);
#pragma unroll
            for (int j = 0; j < 8; j++) {
                float2 t = cmulf2(r[j + 8], wb);
                float2 a = r[j];
                r[j]     = caddf2(a, t);
                r[j + 8] = csubf2(a, t);
                wb = cmulf2(wb, RHOc);
            }
        }
#pragma unroll
        for (int j = 0; j < 16; j++) S[baseCi + (j ^ mm)] = r[j];
    }

    __syncthreads();
    {
        int c = tid >> 4, i0 = tid & 15;
        int baseBi = 256 * c;
        int mB = i0 ^ (8 * (c & 3));
#pragma unroll
        for (int j = 0; j < 16; j++)
            r[j] = S[baseBi + 32 * (j >> 1) + (mB ^ ((16 * (j & 1)) | (j >> 1)))];
        float2 qB;
        { float sn, cs; __sincosf(C8 * (float)(i0 << 5), &sn, &cs); qB = make_float2(cs, sn); }
        {
            float2 v0 = cmulf2(qB, qB); v0 = cmulf2(v0, v0);
#pragma unroll
            for (int q = 0; q < 4; q++) r4i(r[4 * q], r[4 * q + 1], r[4 * q + 2], r[4 * q + 3], v0);
        }
        {
            float2 v = qB;
#pragma unroll
            for (int jp = 0; jp < 4; jp++) {
                r4i(r[jp], r[jp + 4], r[jp + 8], r[jp + 12], v);
                v = cmulf2(v, RHOc);
            }
        }
#pragma unroll
        for (int j = 0; j < 16; j++)
            S[baseBi + 32 * (j >> 1) + (mB ^ ((16 * (j & 1)) | (j >> 1)))] = r[j];
    }

    __syncthreads();
    {
        int e = tid >> 8, i1 = tid & 255;
        int baseA = 4096 * e + (i1 & ~31);
        int mA = (i1 & 31) ^ (i1 >> 5);
#pragma unroll
        for (int j = 0; j < 16; j++) r[j] = S[baseA + 256 * j + (mA ^ (8 * (j & 3)))];
        float2 qA;
        { float sn, cs; __sincosf(C8 * (float)(i1 << 1), &sn, &cs); qA = make_float2(cs, sn); }
        {
            float2 v0 = cmulf2(qA, qA); v0 = cmulf2(v0, v0);
#pragma unroll
            for (int q = 0; q < 4; q++) r4i(r[4 * q], r[4 * q + 1], r[4 * q + 2], r[4 * q + 3], v0);
        }
        {
            float2 v = qA;
#pragma unroll
            for (int jp = 0; jp < 4; jp++) {
                r4i(r[jp], r[jp + 4], r[jp + 8], r[jp + 12], v);
                v = cmulf2(v, RHOc);
            }
        }
#pragma unroll
        for (int j = 0; j < 16; j++) S[baseA + 256 * j + (mA ^ (8 * (j & 3)))] = r[j];
    }

    __syncthreads();
    float Dh = Dv[h];
    int pA = tid ^ (tid >> 5);
    float2 wb;
    { float sn, cs; __sincosf(C8 * (float)tid, &sn, &cs); wb = make_float2(cs, sn); }
#pragma unroll
    for (int p = 0; p < 8; p++) {
        int addr = (pA ^ ((p & 1) << 4)) + 512 * p;
        float2 a = S[addr], bq = S[addr + 4096];
        float2 t = cmulf2(bq, wb);
        float2 X = caddf2(a, t);          // already includes 1/M via prescaled Kf
        int g = tid + 512 * p;
        float2 uu = up[g];
        float y0 = X.x + Dh * uu.x;
        float y1 = X.y + Dh * uu.y;
        float q0 = 0.5f * y0 * (1.0f + erff(y0 * 0.70710678118654752440f));
        float q1 = 0.5f * y1 * (1.0f + erff(y1 * 0.70710678118654752440f));
        __half2* gt = (__half2*)g_T + (((size_t)b * 64 + (g >> 6)) * HDIM + h) * 64 + (g & 63);
        *gt = __floats2half2_rn(q0, q1);
        wb = cmulf2(wb, RHOc);
    }
}

// W pack: plain fp16
extern "C" __global__ void __launch_bounds__(256) wpack_kernel(const float* __restrict__ Wm) {
    int i = blockIdx.x * 256 + threadIdx.x;
    g_Wh[i] = __float2half_rn(Wm[i]);
}

// ---------------- mma.sync GEMM (R15, proven, monolithic grid) ----------------
__device__ __forceinline__ uint32_t smem_u32(const void* p) {
    return (uint32_t)__cvta_generic_to_shared(p);
}
__device__ __forceinline__ uint32_t swz(uint32_t off) { return off ^ ((off >> 3) & 0x70); }
__device__ __forceinline__ uint32_t swzB(uint32_t row, uint32_t colb) {
    return row * 256 + (colb ^ ((row & 7) << 4));
}

__device__ __forceinline__ void ldmat4(uint32_t* r, uint32_t addr) {
    asm volatile("ldmatrix.sync.aligned.m8n8.x4.shared.b16 {%0,%1,%2,%3}, [%4];"
                 : "=r"(r[0]), "=r"(r[1]), "=r"(r[2]), "=r"(r[3]) : "r"(addr));
}
__device__ __forceinline__ void ldmat4t(uint32_t* r, uint32_t addr) {
    asm volatile("ldmatrix.sync.aligned.m8n8.x4.trans.shared.b16 {%0,%1,%2,%3}, [%4];"
                 : "=r"(r[0]), "=r"(r[1]), "=r"(r[2]), "=r"(r[3]) : "r"(addr));
}
__device__ __forceinline__ void mma16816(float* d, const uint32_t* a, uint32_t b0, uint32_t b1) {
    asm volatile(
        "mma.sync.aligned.m16n8k16.row.col.f32.f16.f16.f32 "
        "{%0,%1,%2,%3}, {%4,%5,%6,%7}, {%8,%9}, {%0,%1,%2,%3};"
        : "+f"(d[0]), "+f"(d[1]), "+f"(d[2]), "+f"(d[3])
        : "r"(a[0]), "r"(a[1]), "r"(a[2]), "r"(a[3]), "r"(b0), "r"(b1));
}
#define CP16(dst, src) asm volatile("cp.async.cg.shared.global [%0], [%1], 16;" :: "r"(dst), "l"(src) : "memory")
#define CP_COMMIT()    asm volatile("cp.async.commit_group;" ::: "memory")
#define CP_WAIT1()     asm volatile("cp.async.wait_group 1;" ::: "memory")

extern "C" __global__ void __launch_bounds__(256, 2) gemm_mma_kernel(
    const float* __restrict__ bias, float* __restrict__ outp) {
    extern __shared__ char smem[];
    uint32_t sb = smem_u32(smem);
    int t = threadIdx.x;
    int lane = t & 31, wid = t >> 5;
    int warp_m = wid >> 2, warp_n = wid & 3;
    int o0 = blockIdx.x * 128, l0 = blockIdx.y * 128, b = blockIdx.z;

    int a_row = t >> 1, a_half = t & 1;
    const __half* wp = g_Wh + (size_t)(o0 + a_row) * HDIM + a_half * 32;
    int b_row = t >> 2, b_c4 = t & 3;
    const __half* gpB = g_T + ((size_t)b * 64 + blockIdx.y) * HDIM * 128;

    auto load_chunk = [&](int dc) {
        int buf = dc % 3;
        uint32_t sA = sb + buf * 32768;
        uint32_t sB = sA + 16384;
        const __half* aw = wp + dc * 64;
#pragma unroll
        for (int j = 0; j < 4; j++) {
            uint32_t off = (uint32_t)(a_row * 128 + a_half * 64 + j * 16);
            CP16(sA + swz(off), aw + j * 8);
        }
        const __half* brow = gpB + (size_t)(dc * 64 + b_row) * 128 + b_c4 * 32;
#pragma unroll
        for (int e2 = 0; e2 < 4; e2++) {
            uint32_t colb = (uint32_t)(b_c4 * 64 + e2 * 16);
            CP16(sB + swzB((uint32_t)b_row, colb), brow + e2 * 8);
        }
    };

    int a_lrow = (lane & 7) + ((lane >> 3) & 1) * 8;
    int a_lcol = (lane >> 4) * 16;
    uint32_t xorm = (uint32_t)((lane & 7) << 4);
    int bt_row = (lane & 7) + 8 * ((lane >> 3) & 1);
    int bt_colb = 16 * (lane >> 4);

    float acc[4][4][4];
#pragma unroll
    for (int i = 0; i < 4; i++)
#pragma unroll
        for (int j = 0; j < 4; j++)
#pragma unroll
            for (int q = 0; q < 4; q++) acc[i][j][q] = 0.f;

    load_chunk(0);
    CP_COMMIT();
    load_chunk(1);
    CP_COMMIT();

#pragma unroll 1
    for (int dc = 0; dc < 8; dc++) {
        CP_WAIT1();
        __syncthreads();
        if (dc + 2 < 8) load_chunk(dc + 2);
        CP_COMMIT();
        int buf = dc % 3;
        uint32_t sA = sb + buf * 32768;
        uint32_t sB = sA + 16384;
#pragma unroll
        for (int st = 0; st < 4; st++) {
            int cc = st >> 1, sub = st & 1;
            uint32_t afr[4][4];
#pragma unroll
            for (int mt = 0; mt < 4; mt++) {
                uint32_t off = (uint32_t)((warp_m * 64 + mt * 16 + a_lrow) * 128
                                          + cc * 64 + sub * 32 + a_lcol);
                ldmat4(afr[mt], sA + (off ^ xorm));
            }
#pragma unroll
            for (int bt = 0; bt < 2; bt++) {
                uint32_t bfr[4];
                uint32_t row = (uint32_t)(st * 16 + bt_row);
                uint32_t colb = (uint32_t)(2 * (warp_n * 32 + bt * 16) + bt_colb);
                ldmat4t(bfr, sB + swzB(row, colb));
#pragma unroll
                for (int mt = 0; mt < 4; mt++) {
                    mma16816(acc[mt][bt * 2 + 0], afr[mt], bfr[0], bfr[1]);
                    mma16816(acc[mt][bt * 2 + 1], afr[mt], bfr[2], bfr[3]);
                }
            }
        }
    }

#pragma unroll
    for (int mt = 0; mt < 4; mt++) {
        int r = o0 + warp_m * 64 + mt * 16 + (lane >> 2);
        float bs0 = bias[r], bs1 = bias[r + 8];
        float* p0 = outp + ((size_t)b * HDIM + r) * LDIM + l0 + warp_n * 32 + (lane & 3) * 2;
        float* p1 = p0 + 8 * LDIM;
#pragma unroll
        for (int nt = 0; nt < 4; nt++) {
            float2 v0 = make_float2(acc[mt][nt][0] + bs0, acc[mt][nt][1] + bs0);
            float2 v1 = make_float2(acc[mt][nt][2] + bs1, acc[mt][nt][3] + bs1);
            *(float2*)(p0 + nt * 8) = v0;
            *(float2*)(p1 + nt * 8) = v1;
        }
    }
}

extern "C" void kernel_launch(void* const* d_in, const int* in_sizes, int n_in,
                              void* d_out, int out_size) {
    const float* u    = (const float*)d_in[0];   // (8,512,8192)
    const float* kin  = (const float*)d_in[1];   // (1,512,8192)
    const float* Dv   = (const float*)d_in[2];   // (1,512)
    const float* Wm   = (const float*)d_in[3];   // (512,512)
    const float* bias = (const float*)d_in[4];   // (512,)
    float* outp = (float*)d_out;                 // (8,512,8192)

    size_t smem = (size_t)MFFT * sizeof(float2);  // 64 KB
    cudaFuncSetAttribute(kf_kernel,   cudaFuncAttributeMaxDynamicSharedMemorySize, (int)smem);
    cudaFuncSetAttribute(conv_kernel, cudaFuncAttributeMaxDynamicSharedMemorySize, (int)smem);
    size_t gsmem = 3 * 32768;                      // 96 KB
    cudaFuncSetAttribute(gemm_mma_kernel, cudaFuncAttributeMaxDynamicSharedMemorySize, (int)gsmem);

    wpack_kernel<<<HDIM * HDIM / 256, 256>>>(Wm);
    kf_kernel<<<HDIM, 512, smem>>>(kin);
    conv_kernel<<<BDIM * HDIM, 512, smem>>>(u, Dv);
    dim3 grid(HDIM / 128, LDIM / 128, BDIM);
    gemm_mma_kernel<<<grid, 256, gsmem>>>(bias, outp);
}